// round 1
// baseline (speedup 1.0000x reference)
#include <cuda_runtime.h>
#include <math.h>

#define NROWS 4096
#define DIMH  1024
#define DIN2  2048

// ---------------- device helpers ----------------
__device__ __forceinline__ float srelu(float x){
    float r = fmaxf(x, 0.0f);
    if (r < 0.1f){ float r2 = r*r; return (0.2f*r*r2 - r2*r2) * 500.0f; }
    return x - 0.05f;
}
__device__ __forceinline__ float softplusf(float x){
    return fmaxf(x, 0.0f) + log1pf(expf(-fabsf(x)));
}

// ---------------- scratch (device globals: allocation-guard safe) ----------------
__device__ float g_Pt [DIMH*DIMH];     // P^T (full)
__device__ float g_Psc[DIMH*DIMH];     // eig-scaled P, row 0 zeroed
__device__ float g_Lm [DIMH*DIMH];
__device__ float g_Hu [NROWS*DIMH];
__device__ float g_st [NROWS*DIN2];
__device__ float g_G1 [NROWS*DIMH];
__device__ float g_W1t[DIN2*512];
__device__ float g_W2t[512*512];
__device__ float g_W3t[512*DIN2];
__device__ float g_icWt[DIN2*128];     // [icW0^T | icW1^T]
__device__ float g_H1 [NROWS*512];
__device__ float g_H2 [NROWS*512];
__device__ float g_CT [NROWS*DIN2];
__device__ float g_Z01[NROWS*128];
__device__ float g_Z2 [NROWS*64];
__device__ float g_spU0[64*64];
__device__ float g_spU1[64];
__device__ float g_cb01[128];
__device__ float g_z0[1];

// ---------------- transpose: dst[c*LD + OFF + r] = src[r*C + c] ----------------
__global__ void transposeK(const float* __restrict__ src, float* __restrict__ dst,
                           int R, int C, int LD, int OFF){
    __shared__ float tile[32][33];
    int c0 = blockIdx.x*32, r0 = blockIdx.y*32;
    int x = threadIdx.x, y = threadIdx.y;
    #pragma unroll
    for (int i=0;i<32;i+=8){
        int r = r0 + y + i, c = c0 + x;
        if (r < R && c < C) tile[y+i][x] = src[(size_t)r*C + c];
    }
    __syncthreads();
    #pragma unroll
    for (int i=0;i<32;i+=8){
        int c = c0 + y + i;   // dst row index (source column)
        int r = r0 + x;       // dst col index (source row)
        if (c < C && r < R) dst[(size_t)c*LD + OFF + r] = tile[x][y+i];
    }
}

// ---------------- Psc = eig(i) * P[i,:], row 0 = 0 ----------------
__global__ void pscK(const float* __restrict__ P, const float* __restrict__ t,
                     float* __restrict__ Psc){
    int idx = blockIdx.x*blockDim.x + threadIdx.x;
    int i = idx >> 10;
    float s = 2.0f * sinf(t[0]);
    float e = (i == 0) ? 0.0f : ((i <= 511) ? (1.0f + s) : (1.0f - s));
    Psc[idx] = e * P[idx];
}

// ---------------- Hu = sigmoid(10*u), st = x - x[col0 of its half] ----------------
__global__ void huStK(const float* __restrict__ state){
    int idx = blockIdx.x*blockDim.x + threadIdx.x;   // over NROWS*DIN2
    int n = idx >> 11, d = idx & 2047;
    float x  = state[idx];
    float x0 = state[(n<<11) + (d < DIMH ? 0 : DIMH)];
    g_st[idx] = x - x0;
    if (d < DIMH) g_Hu[n*DIMH + d] = 1.0f/(1.0f + expf(-10.0f*x));
}

// ---------------- softplus(U), concat biases, z0 constant ----------------
__global__ void prepIcnnK(const float* __restrict__ icU0, const float* __restrict__ icU1,
                          const float* __restrict__ icb0, const float* __restrict__ icb1,
                          const float* __restrict__ icb2){
    int tid = threadIdx.x;
    for (int i = tid; i < 64*64; i += blockDim.x) g_spU0[i] = softplusf(icU0[i]);
    if (tid < 64){
        g_spU1[tid]     = softplusf(icU1[tid]);
        g_cb01[tid]     = icb0[tid];
        g_cb01[64+tid]  = icb1[tid];
    }
    __syncthreads();
    __shared__ float z0a[64], z0b[64];
    if (tid < 64) z0a[tid] = srelu(icb0[tid]);
    __syncthreads();
    if (tid < 64){
        float s = icb1[tid];
        #pragma unroll 8
        for (int j=0;j<64;j++) s += g_spU0[tid*64+j]*z0a[j];
        z0b[tid] = srelu(s);
    }
    __syncthreads();
    if (tid == 0){
        float s = icb2[0];
        for (int j=0;j<64;j++) s += g_spU1[j]*z0b[j];
        g_z0[0] = srelu(s);
    }
}

// ---------------- z2 = srelu(Z01[:,64:] + spU0 @ srelu(Z01[:,:64])) ----------------
__global__ void z2K(){
    int n = blockIdx.x;
    int k = threadIdx.x;  // 64 threads
    __shared__ float z1s[64];
    z1s[k] = srelu(g_Z01[n*128 + k]);
    __syncthreads();
    float s = g_Z01[n*128 + 64 + k];
    #pragma unroll 8
    for (int j=0;j<64;j++) s += g_spU0[k*64+j]*z1s[j];
    g_Z2[n*64 + k] = srelu(s);
}

// ---------------- final assembly: du, dv, ctrl clamp, ICNN V ----------------
__global__ void finalK(const float* __restrict__ state, const float* __restrict__ icW2,
                       const float* __restrict__ icb2, float* __restrict__ out){
    int n = blockIdx.x;
    int tid = threadIdx.x;  // 256
    const float* srow = state + (size_t)n*DIN2;

    float dot = 0.0f, ss = 0.0f;
    for (int d = tid; d < DIN2; d += 256){
        float x = srow[d];
        dot = fmaf(icW2[d], x, dot);
        ss  = fmaf(x, x, ss);
    }
    #pragma unroll
    for (int o=16;o>0;o>>=1){
        dot += __shfl_down_sync(0xffffffffu, dot, o);
        ss  += __shfl_down_sync(0xffffffffu, ss,  o);
    }
    __shared__ float sd[8], sq[8];
    if ((tid & 31) == 0){ sd[tid>>5] = dot; sq[tid>>5] = ss; }
    __syncthreads();
    if (tid == 0){
        float D = 0.0f, S = 0.0f;
        #pragma unroll
        for (int w=0;w<8;w++){ D += sd[w]; S += sq[w]; }
        float z = icb2[0] + D;
        for (int k=0;k<64;k++) z = fmaf(g_spU1[k], g_Z2[n*64+k], z);
        float z3 = srelu(z);
        out[(size_t)n*2049 + 2048] = srelu(z3 - g_z0[0]) + 0.001f*S;
    }

    for (int d = tid; d < DIN2; d += 256){
        float sv = g_st[(size_t)n*DIN2 + d];
        float ux = g_CT[(size_t)n*DIN2 + d] * sv;   // (h2@W3.T + b3) * st
        float ctrl = (ux < 10.0f && ux > -10.0f) ? ux : 0.0f;
        float val;
        if (d < DIMH){
            float uu = srow[d], vv = srow[DIMH + d];
            val = uu - uu*uu*uu*(1.0f/3.0f) - vv + 1.0f + g_G1[(size_t)n*DIMH + d] + ctrl;
        } else {
            float uu = srow[d - DIMH], vv = srow[d];
            val = 0.2f*(uu + 0.7f - 0.8f*vv) + ctrl;
        }
        out[(size_t)n*2049 + d] = val;
    }
}

// ---------------- tiled SGEMM: C[M,N] = A[M,K] @ B[K,N] (+bias, epilogue) ----------------
// EPI: 0 = none, 1 = tanh, 2 = srelu. Requires M%BM==0, N%BN==0, K%BK==0, BK%4==0.
template<int BM,int BN,int BK,int TM,int TN,int EPI>
__global__ __launch_bounds__((BM/TM)*(BN/TN))
void sgemm(int M, int N, int K,
           const float* __restrict__ A, const float* __restrict__ B,
           const float* __restrict__ bias, float* __restrict__ C){
    constexpr int THREADS = (BM/TM)*(BN/TN);
    __shared__ float As[BK][BM];
    __shared__ float Bs[BK][BN];
    const int tid  = threadIdx.x;
    const int bm   = blockIdx.y*BM, bn = blockIdx.x*BN;
    const int tcol = tid % (BN/TN);
    const int trow = tid / (BN/TN);

    float acc[TM][TN];
    #pragma unroll
    for (int i=0;i<TM;i++)
        #pragma unroll
        for (int j=0;j<TN;j++) acc[i][j] = 0.0f;

    const float* Ab = A + (size_t)bm*K;
    const float* Bb = B + bn;

    for (int k0 = 0; k0 < K; k0 += BK){
        #pragma unroll
        for (int i = tid*4; i < BM*BK; i += THREADS*4){
            int r = i / BK, c = i % BK;
            float4 v = *reinterpret_cast<const float4*>(Ab + (size_t)r*K + k0 + c);
            As[c+0][r] = v.x; As[c+1][r] = v.y; As[c+2][r] = v.z; As[c+3][r] = v.w;
        }
        #pragma unroll
        for (int i = tid*4; i < BK*BN; i += THREADS*4){
            int r = i / BN, c = i % BN;
            *reinterpret_cast<float4*>(&Bs[r][c]) =
                *reinterpret_cast<const float4*>(Bb + (size_t)(k0+r)*N + c);
        }
        __syncthreads();
        #pragma unroll
        for (int kk=0;kk<BK;kk++){
            float ra[TM], rb[TN];
            #pragma unroll
            for (int i=0;i<TM;i++) ra[i] = As[kk][trow*TM+i];
            #pragma unroll
            for (int j=0;j<TN;j++) rb[j] = Bs[kk][tcol*TN+j];
            #pragma unroll
            for (int i=0;i<TM;i++)
                #pragma unroll
                for (int j=0;j<TN;j++)
                    acc[i][j] = fmaf(ra[i], rb[j], acc[i][j]);
        }
        __syncthreads();
    }

    #pragma unroll
    for (int i=0;i<TM;i++){
        int row = bm + trow*TM + i;
        #pragma unroll
        for (int j=0;j<TN;j++){
            int col = bn + tcol*TN + j;
            float v = acc[i][j];
            if (bias) v += bias[col];
            if (EPI == 1) v = tanhf(v);
            else if (EPI == 2) v = srelu(v);
            C[(size_t)row*N + col] = v;
        }
    }
}

// ---------------- host ----------------
extern "C" void kernel_launch(void* const* d_in, const int* in_sizes, int n_in,
                              void* d_out, int out_size){
    const float* state = (const float*)d_in[0];
    const float* t     = (const float*)d_in[1];
    const float* P     = (const float*)d_in[2];
    const float* W1    = (const float*)d_in[3];
    const float* b1    = (const float*)d_in[4];
    const float* W2    = (const float*)d_in[5];
    const float* b2    = (const float*)d_in[6];
    const float* W3    = (const float*)d_in[7];
    const float* b3    = (const float*)d_in[8];
    const float* icW0  = (const float*)d_in[9];
    const float* icb0  = (const float*)d_in[10];
    const float* icW1  = (const float*)d_in[11];
    const float* icb1  = (const float*)d_in[12];
    const float* icW2  = (const float*)d_in[13];
    const float* icb2  = (const float*)d_in[14];
    const float* icU0  = (const float*)d_in[15];
    const float* icU1  = (const float*)d_in[16];
    float* out = (float*)d_out;

    float *Pt, *Psc, *Lm, *Hu, *st, *G1, *W1t, *W2t, *W3t, *icWt, *H1, *H2, *CT, *Z01, *cb01;
    cudaGetSymbolAddress((void**)&Pt,   g_Pt);
    cudaGetSymbolAddress((void**)&Psc,  g_Psc);
    cudaGetSymbolAddress((void**)&Lm,   g_Lm);
    cudaGetSymbolAddress((void**)&Hu,   g_Hu);
    cudaGetSymbolAddress((void**)&st,   g_st);
    cudaGetSymbolAddress((void**)&G1,   g_G1);
    cudaGetSymbolAddress((void**)&W1t,  g_W1t);
    cudaGetSymbolAddress((void**)&W2t,  g_W2t);
    cudaGetSymbolAddress((void**)&W3t,  g_W3t);
    cudaGetSymbolAddress((void**)&icWt, g_icWt);
    cudaGetSymbolAddress((void**)&H1,   g_H1);
    cudaGetSymbolAddress((void**)&H2,   g_H2);
    cudaGetSymbolAddress((void**)&CT,   g_CT);
    cudaGetSymbolAddress((void**)&Z01,  g_Z01);
    cudaGetSymbolAddress((void**)&cb01, g_cb01);

    dim3 tb(32, 8);
    // P^T (full; Psc zeroes row 0 so the i=0 column contributes nothing)
    transposeK<<<dim3(32,32), tb>>>(P,   Pt,  1024, 1024, 1024, 0);
    // weight transposes
    transposeK<<<dim3(64,16), tb>>>(W1,  W1t,  512, 2048,  512, 0);
    transposeK<<<dim3(16,16), tb>>>(W2,  W2t,  512,  512,  512, 0);
    transposeK<<<dim3(16,64), tb>>>(W3,  W3t, 2048,  512, 2048, 0);
    transposeK<<<dim3(64, 2), tb>>>(icW0, icWt,  64, 2048,  128, 0);
    transposeK<<<dim3(64, 2), tb>>>(icW1, icWt,  64, 2048,  128, 64);

    pscK<<<(1024*1024)/256, 256>>>(P, t, Psc);
    prepIcnnK<<<1, 256>>>(icU0, icU1, icb0, icb1, icb2);
    huStK<<<(NROWS*DIN2)/256, 256>>>(state);

    // Lm = Pt @ Psc  (1024x1024x1024) — 128x64 tile => 128 CTAs
    sgemm<128,64,8,8,4,0><<<dim3(1024/64, 1024/128), 256>>>(1024, 1024, 1024, Pt, Psc, nullptr, Lm);
    // G1 = Hu @ Lm  (4096x1024x1024)
    sgemm<128,128,8,8,8,0><<<dim3(1024/128, NROWS/128), 256>>>(NROWS, 1024, 1024, Hu, Lm, nullptr, G1);
    // H1 = tanh(st @ W1t + b1)  (4096x512x2048)
    sgemm<128,128,8,8,8,1><<<dim3(512/128, NROWS/128), 256>>>(NROWS, 512, 2048, st, W1t, b1, H1);
    // H2 = tanh(H1 @ W2t + b2)  (4096x512x512)
    sgemm<128,128,8,8,8,1><<<dim3(512/128, NROWS/128), 256>>>(NROWS, 512, 512, H1, W2t, b2, H2);
    // CT = H2 @ W3t + b3  (4096x2048x512)
    sgemm<128,128,8,8,8,0><<<dim3(2048/128, NROWS/128), 256>>>(NROWS, 2048, 512, H2, W3t, b3, CT);
    // Z01 = state @ [icW0t|icW1t] + [icb0;icb1]  (4096x128x2048)
    sgemm<64,64,8,4,4,0><<<dim3(128/64, NROWS/64), 256>>>(NROWS, 128, 2048, state, icWt, cb01, Z01);

    z2K<<<NROWS, 64>>>();
    finalK<<<NROWS, 256>>>(state, icW2, icb2, out);
}

// round 2
// speedup vs baseline: 2.4609x; 2.4609x over previous
#include <cuda_runtime.h>
#include <math.h>
#include <stdint.h>

#define NROWS 4096
#define DIMH  1024
#define DIN2  2048

// ---------------- device helpers ----------------
__device__ __forceinline__ float srelu(float x){
    float r = fmaxf(x, 0.0f);
    if (r < 0.1f){ float r2 = r*r; return (0.2f*r*r2 - r2*r2) * 500.0f; }
    return x - 0.05f;
}
__device__ __forceinline__ float softplusf(float x){
    return fmaxf(x, 0.0f) + log1pf(expf(-fabsf(x)));
}

// ---------------- scratch (device globals: allocation-guard safe) ----------------
__device__ float g_Pt  [DIMH*DIMH];     // Pt[a][i]  = P[i][a]
__device__ float g_PtSc[DIMH*DIMH];     // PtSc[a][i]= e_i * P[i][a], e_0 = 0
__device__ float g_Lm  [DIMH*DIMH];
__device__ float g_Hu  [NROWS*DIMH];
__device__ float g_st  [NROWS*DIN2];
__device__ float g_G1  [NROWS*DIMH];
__device__ float g_icWcat[128*DIN2];    // [icW0 ; icW1] rows, [N=128][K=2048]
__device__ float g_H1  [NROWS*512];
__device__ float g_H2  [NROWS*512];
__device__ float g_CT  [NROWS*DIN2];
__device__ float g_Z01 [NROWS*128];
__device__ float g_Z2  [NROWS*64];
__device__ float g_spU0[64*64];
__device__ float g_spU1[64];
__device__ float g_cb01[128];
__device__ float g_z0[1];

// ---------------- fused P transpose + eig scale ----------------
__global__ void transposePK(const float* __restrict__ P, const float* __restrict__ t,
                            float* __restrict__ Pt, float* __restrict__ PtSc){
    __shared__ float tile[32][33];
    int c0 = blockIdx.x*32, r0 = blockIdx.y*32;
    int x = threadIdx.x, y = threadIdx.y;
    float s = 2.0f * sinf(t[0]);
    #pragma unroll
    for (int i=0;i<32;i+=8)
        tile[y+i][x] = P[(size_t)(r0+y+i)*DIMH + c0 + x];
    __syncthreads();
    #pragma unroll
    for (int i=0;i<32;i+=8){
        int c = c0 + y + i;       // dst row (source column a)
        int r = r0 + x;           // dst col (source row i)
        float v = tile[x][y+i];
        float e = (r == 0) ? 0.0f : ((r <= 511) ? (1.0f + s) : (1.0f - s));
        Pt  [(size_t)c*DIMH + r] = v;
        PtSc[(size_t)c*DIMH + r] = e * v;
    }
}

// ---------------- concat icW0/icW1 ----------------
__global__ void catIcWK(const float* __restrict__ w0, const float* __restrict__ w1){
    int i = blockIdx.x*256 + threadIdx.x;     // 0 .. 64*2048-1
    g_icWcat[i]             = w0[i];
    g_icWcat[64*DIN2 + i]   = w1[i];
}

// ---------------- Hu = sigmoid(10*u), st = x - x[col0 of its half] ----------------
__global__ void huStK(const float* __restrict__ state){
    int idx = blockIdx.x*blockDim.x + threadIdx.x;   // over NROWS*DIN2
    int n = idx >> 11, d = idx & 2047;
    float x  = state[idx];
    float x0 = state[(n<<11) + (d < DIMH ? 0 : DIMH)];
    g_st[idx] = x - x0;
    if (d < DIMH) g_Hu[n*DIMH + d] = 1.0f/(1.0f + expf(-10.0f*x));
}

// ---------------- softplus(U), concat biases, z0 constant ----------------
__global__ void prepIcnnK(const float* __restrict__ icU0, const float* __restrict__ icU1,
                          const float* __restrict__ icb0, const float* __restrict__ icb1,
                          const float* __restrict__ icb2){
    int tid = threadIdx.x;
    for (int i = tid; i < 64*64; i += blockDim.x) g_spU0[i] = softplusf(icU0[i]);
    if (tid < 64){
        g_spU1[tid]     = softplusf(icU1[tid]);
        g_cb01[tid]     = icb0[tid];
        g_cb01[64+tid]  = icb1[tid];
    }
    __syncthreads();
    __shared__ float z0a[64], z0b[64];
    if (tid < 64) z0a[tid] = srelu(icb0[tid]);
    __syncthreads();
    if (tid < 64){
        float s = icb1[tid];
        #pragma unroll 8
        for (int j=0;j<64;j++) s += g_spU0[tid*64+j]*z0a[j];
        z0b[tid] = srelu(s);
    }
    __syncthreads();
    if (tid == 0){
        float s = icb2[0];
        for (int j=0;j<64;j++) s += g_spU1[j]*z0b[j];
        g_z0[0] = srelu(s);
    }
}

// ---------------- z2 = srelu(Z01[:,64:] + spU0 @ srelu(Z01[:,:64])) ----------------
__global__ void z2K(){
    int n = blockIdx.x;
    int k = threadIdx.x;  // 64 threads
    __shared__ float z1s[64];
    z1s[k] = srelu(g_Z01[n*128 + k]);
    __syncthreads();
    float s = g_Z01[n*128 + 64 + k];
    #pragma unroll 8
    for (int j=0;j<64;j++) s += g_spU0[k*64+j]*z1s[j];
    g_Z2[n*64 + k] = srelu(s);
}

// ---------------- final assembly: du, dv, ctrl clamp, ICNN V ----------------
__global__ void finalK(const float* __restrict__ state, const float* __restrict__ icW2,
                       const float* __restrict__ icb2, float* __restrict__ out){
    int n = blockIdx.x;
    int tid = threadIdx.x;  // 256
    const float* srow = state + (size_t)n*DIN2;

    float dot = 0.0f, ss = 0.0f;
    for (int d = tid; d < DIN2; d += 256){
        float x = srow[d];
        dot = fmaf(icW2[d], x, dot);
        ss  = fmaf(x, x, ss);
    }
    #pragma unroll
    for (int o=16;o>0;o>>=1){
        dot += __shfl_down_sync(0xffffffffu, dot, o);
        ss  += __shfl_down_sync(0xffffffffu, ss,  o);
    }
    __shared__ float sd[8], sq[8];
    if ((tid & 31) == 0){ sd[tid>>5] = dot; sq[tid>>5] = ss; }
    __syncthreads();
    if (tid == 0){
        float D = 0.0f, S = 0.0f;
        #pragma unroll
        for (int w=0;w<8;w++){ D += sd[w]; S += sq[w]; }
        float z = icb2[0] + D;
        for (int k=0;k<64;k++) z = fmaf(g_spU1[k], g_Z2[n*64+k], z);
        float z3 = srelu(z);
        out[(size_t)n*2049 + 2048] = srelu(z3 - g_z0[0]) + 0.001f*S;
    }

    for (int d = tid; d < DIN2; d += 256){
        float sv = g_st[(size_t)n*DIN2 + d];
        float ux = g_CT[(size_t)n*DIN2 + d] * sv;
        float ctrl = (ux < 10.0f && ux > -10.0f) ? ux : 0.0f;
        float val;
        if (d < DIMH){
            float uu = srow[d], vv = srow[DIMH + d];
            val = uu - uu*uu*uu*(1.0f/3.0f) - vv + 1.0f + g_G1[(size_t)n*DIMH + d] + ctrl;
        } else {
            float uu = srow[d - DIMH], vv = srow[d];
            val = 0.2f*(uu + 0.7f - 0.8f*vv) + ctrl;
        }
        out[(size_t)n*2049 + d] = val;
    }
}

// ---------------- TF32 tensor-core GEMM ----------------
// C[M,N] = A[M,K] @ Bt[N,K]^T (+bias[col], EPI: 0 none, 1 tanh)
// Requires M%BM==0, N%BN==0, K%16==0. 256 threads.
#define CPASYNC(dst, src) asm volatile("cp.async.cg.shared.global [%0], [%1], 16;\n" :: "r"(dst), "l"(src))
#define CPCOMMIT()        asm volatile("cp.async.commit_group;\n" ::: "memory")
#define CPWAIT0()         asm volatile("cp.async.wait_group 0;\n" ::: "memory")

__device__ __forceinline__ void ldsm4(uint32_t addr, uint32_t& r0, uint32_t& r1,
                                      uint32_t& r2, uint32_t& r3){
    asm volatile("ldmatrix.sync.aligned.m8n8.x4.shared.b16 {%0,%1,%2,%3}, [%4];"
                 : "=r"(r0), "=r"(r1), "=r"(r2), "=r"(r3) : "r"(addr));
}
__device__ __forceinline__ void mma_tf32(float* d, const uint32_t* a4,
                                         uint32_t b0, uint32_t b1){
    // A operand order for m16n8k8 tf32: {a0,a1,a2,a3} = {r0, r2, r1, r3} of ldmatrix
    asm volatile("mma.sync.aligned.m16n8k8.row.col.f32.tf32.tf32.f32 "
                 "{%0,%1,%2,%3}, {%4,%5,%6,%7}, {%8,%9}, {%0,%1,%2,%3};"
                 : "+f"(d[0]), "+f"(d[1]), "+f"(d[2]), "+f"(d[3])
                 : "r"(a4[0]), "r"(a4[2]), "r"(a4[1]), "r"(a4[3]),
                   "r"(b0), "r"(b1));
}

template<int BM, int BN, int EPI>
__global__ __launch_bounds__(256)
void mmaGemm(int M, int N, int K,
             const float* __restrict__ A, const float* __restrict__ Bt,
             const float* __restrict__ bias, float* __restrict__ C){
    constexpr int BK  = 16;
    constexpr int LDS = BK + 4;                 // 20 floats = 80B row stride (16B aligned, LDSM conflict-free)
    constexpr int WARPS_M = BM/32;              // 32 M-rows per warp (2 m-tiles)
    constexpr int WARPS_N = 8/WARPS_M;
    constexpr int WN = BN/WARPS_N;              // warp N span
    constexpr int NP = WN/16;                   // B ldmatrix.x4 pairs per warp per k-step

    __shared__ __align__(16) float As[2][BM*LDS];
    __shared__ __align__(16) float Bs[2][BN*LDS];

    const int tid  = threadIdx.x;
    const int warp = tid >> 5, lane = tid & 31;
    const int wm = (warp % WARPS_M)*32;
    const int wn = (warp / WARPS_M)*WN;
    const int bm = blockIdx.y*BM, bn = blockIdx.x*BN;

    const int lrow   = ((lane>>4)&1)*8 + (lane&7);   // ldmatrix row within 16-row tile
    const int lcol16 = ((lane>>3)&1)*16;             // byte offset (tf32 col 0 / 4)

    float acc[2][2*NP][4];
    #pragma unroll
    for (int i=0;i<2;i++)
        #pragma unroll
        for (int j=0;j<2*NP;j++)
            #pragma unroll
            for (int q=0;q<4;q++) acc[i][j][q] = 0.0f;

    const float* Ag = A  + (size_t)bm*K;
    const float* Bg = Bt + (size_t)bn*K;
    uint32_t asBase = (uint32_t)__cvta_generic_to_shared(&As[0][0]);
    uint32_t bsBase = (uint32_t)__cvta_generic_to_shared(&Bs[0][0]);

    auto loadTile = [&](int buf, int k0){
        uint32_t aB = asBase + buf*(BM*LDS*4);
        #pragma unroll
        for (int i=0;i<(BM*4)/256;i++){
            int L = tid + i*256;
            int r = L>>2, s = L&3;
            CPASYNC(aB + (r*LDS + s*4)*4, Ag + (size_t)r*K + k0 + s*4);
        }
        uint32_t bB = bsBase + buf*(BN*LDS*4);
        #pragma unroll
        for (int i=0;i<(BN*4)/256;i++){
            int L = tid + i*256;
            int r = L>>2, s = L&3;
            CPASYNC(bB + (r*LDS + s*4)*4, Bg + (size_t)r*K + k0 + s*4);
        }
        CPCOMMIT();
    };

    loadTile(0, 0);
    CPWAIT0();
    __syncthreads();

    const int nk = K / BK;
    int buf = 0;
    for (int ck = 0; ck < nk; ck++){
        if (ck + 1 < nk) loadTile(buf^1, (ck+1)*BK);

        uint32_t aB = asBase + buf*(BM*LDS*4);
        uint32_t bB = bsBase + buf*(BN*LDS*4);
        #pragma unroll
        for (int s=0; s<2; s++){
            uint32_t af[2][4];
            #pragma unroll
            for (int mt=0; mt<2; mt++)
                ldsm4(aB + (uint32_t)((wm + mt*16 + lrow)*LDS*4) + lcol16 + s*32,
                      af[mt][0], af[mt][1], af[mt][2], af[mt][3]);
            uint32_t bf[NP][4];
            #pragma unroll
            for (int p=0; p<NP; p++)
                ldsm4(bB + (uint32_t)((wn + p*16 + lrow)*LDS*4) + lcol16 + s*32,
                      bf[p][0], bf[p][1], bf[p][2], bf[p][3]);
            #pragma unroll
            for (int mt=0; mt<2; mt++)
                #pragma unroll
                for (int p=0; p<NP; p++){
                    mma_tf32(acc[mt][2*p+0], af[mt], bf[p][0], bf[p][1]);
                    mma_tf32(acc[mt][2*p+1], af[mt], bf[p][2], bf[p][3]);
                }
        }
        CPWAIT0();
        __syncthreads();
        buf ^= 1;
    }

    // epilogue: c0:(g, 2tg) c1:(g, 2tg+1) c2:(g+8, 2tg) c3:(g+8, 2tg+1)
    const int tg = lane & 3, g = lane >> 2;
    #pragma unroll
    for (int mt=0; mt<2; mt++){
        #pragma unroll
        for (int nt=0; nt<2*NP; nt++){
            int row = bm + wm + mt*16 + g;
            int col = bn + wn + nt*8 + tg*2;
            float v0 = acc[mt][nt][0], v1 = acc[mt][nt][1];
            float v2 = acc[mt][nt][2], v3 = acc[mt][nt][3];
            if (bias){
                float b0v = bias[col], b1v = bias[col+1];
                v0 += b0v; v1 += b1v; v2 += b0v; v3 += b1v;
            }
            if (EPI == 1){ v0 = tanhf(v0); v1 = tanhf(v1); v2 = tanhf(v2); v3 = tanhf(v3); }
            float2* p0 = reinterpret_cast<float2*>(C + (size_t)row*N + col);
            float2* p1 = reinterpret_cast<float2*>(C + (size_t)(row+8)*N + col);
            *p0 = make_float2(v0, v1);
            *p1 = make_float2(v2, v3);
        }
    }
}

// ---------------- host ----------------
extern "C" void kernel_launch(void* const* d_in, const int* in_sizes, int n_in,
                              void* d_out, int out_size){
    const float* state = (const float*)d_in[0];
    const float* t     = (const float*)d_in[1];
    const float* P     = (const float*)d_in[2];
    const float* W1    = (const float*)d_in[3];
    const float* b1    = (const float*)d_in[4];
    const float* W2    = (const float*)d_in[5];
    const float* b2    = (const float*)d_in[6];
    const float* W3    = (const float*)d_in[7];
    const float* b3    = (const float*)d_in[8];
    const float* icW0  = (const float*)d_in[9];
    const float* icb0  = (const float*)d_in[10];
    const float* icW1  = (const float*)d_in[11];
    const float* icb1  = (const float*)d_in[12];
    const float* icW2  = (const float*)d_in[13];
    const float* icb2  = (const float*)d_in[14];
    const float* icU0  = (const float*)d_in[15];
    const float* icU1  = (const float*)d_in[16];
    float* out = (float*)d_out;

    float *Pt, *PtSc, *Lm, *Hu, *st, *G1, *icWcat, *H1, *H2, *CT, *Z01, *cb01;
    cudaGetSymbolAddress((void**)&Pt,     g_Pt);
    cudaGetSymbolAddress((void**)&PtSc,   g_PtSc);
    cudaGetSymbolAddress((void**)&Lm,     g_Lm);
    cudaGetSymbolAddress((void**)&Hu,     g_Hu);
    cudaGetSymbolAddress((void**)&st,     g_st);
    cudaGetSymbolAddress((void**)&G1,     g_G1);
    cudaGetSymbolAddress((void**)&icWcat, g_icWcat);
    cudaGetSymbolAddress((void**)&H1,     g_H1);
    cudaGetSymbolAddress((void**)&H2,     g_H2);
    cudaGetSymbolAddress((void**)&CT,     g_CT);
    cudaGetSymbolAddress((void**)&Z01,    g_Z01);
    cudaGetSymbolAddress((void**)&cb01,   g_cb01);

    transposePK<<<dim3(32,32), dim3(32,8)>>>(P, t, Pt, PtSc);
    catIcWK<<<(64*DIN2)/256, 256>>>(icW0, icW1);
    prepIcnnK<<<1, 256>>>(icU0, icU1, icb0, icb1, icb2);
    huStK<<<(NROWS*DIN2)/256, 256>>>(state);

    // Lm = PtSc @ Pt^T        (1024 x 1024 x 1024), Bt = Pt
    mmaGemm<64,128,0><<<dim3(1024/128, 1024/64), 256>>>(1024, 1024, 1024, PtSc, Pt, nullptr, Lm);
    // G1 = Hu @ Lm^T = Hu@Lm  (4096 x 1024 x 1024), Lm symmetric
    mmaGemm<128,128,0><<<dim3(1024/128, NROWS/128), 256>>>(NROWS, 1024, 1024, Hu, Lm, nullptr, G1);
    // H1 = tanh(st @ W1^T + b1)   (4096 x 512 x 2048), Bt = W1 [512][2048]
    mmaGemm<128,128,1><<<dim3(512/128, NROWS/128), 256>>>(NROWS, 512, 2048, st, W1, b1, H1);
    // H2 = tanh(H1 @ W2^T + b2)   (4096 x 512 x 512)
    mmaGemm<128,128,1><<<dim3(512/128, NROWS/128), 256>>>(NROWS, 512, 512, H1, W2, b2, H2);
    // CT = H2 @ W3^T + b3         (4096 x 2048 x 512), Bt = W3 [2048][512]
    mmaGemm<128,128,0><<<dim3(2048/128, NROWS/128), 256>>>(NROWS, 2048, 512, H2, W3, b3, CT);
    // Z01 = state @ icWcat^T + cb01  (4096 x 128 x 2048)
    mmaGemm<64,128,0><<<dim3(128/128, NROWS/64), 256>>>(NROWS, 128, 2048, state, icWcat, cb01, Z01);

    z2K<<<NROWS, 64>>>();
    finalK<<<NROWS, 256>>>(state, icW2, icb2, out);
}